// round 11
// baseline (speedup 1.0000x reference)
#include <cuda_runtime.h>
#include <cuda_fp16.h>
#include <cstdint>
#include <math.h>

#define BB  4
#define TT  2048
#define CC  1024
#define HH  16
#define DD  64
#define WFF 4096
#define MM  (BB*TT)   // 8192
#define C3  (3*CC)    // 3072
#define GRID_P 296    // 148 SMs x 2 CTAs

// ---------------- scratch (device globals: allocation-free) ----------------
__device__ __half g_h  [(size_t)MM*CC];
__device__ __half g_qkv[(size_t)MM*C3];
__device__ __half g_y  [(size_t)MM*CC];
__device__ float  g_x2 [(size_t)MM*CC];
__device__ __half g_ff [(size_t)MM*WFF];
__device__ __half g_wT [(size_t)4*CC*CC + (size_t)2*CC*WFF];
__device__ float  g_bqkv[C3];

// ---------------- helpers ----------------------------------------------------
__device__ __forceinline__ uint32_t smem_u32(const void* p) {
    uint32_t a;
    asm("{ .reg .u64 t; cvta.to.shared.u64 t, %1; cvt.u32.u64 %0, t; }"
        : "=r"(a) : "l"(p));
    return a;
}
__device__ __forceinline__ void cp16(uint32_t s, const void* g) {
    asm volatile("cp.async.cg.shared.global [%0], [%1], 16;"
                 :: "r"(s), "l"(g) : "memory");
}
#define CP_COMMIT() asm volatile("cp.async.commit_group;" ::: "memory")
#define CP_WAIT0()  asm volatile("cp.async.wait_group 0;" ::: "memory")
#define CP_WAIT1()  asm volatile("cp.async.wait_group 1;" ::: "memory")

__device__ __forceinline__ void ldsm4(uint32_t* r, uint32_t a) {
    asm volatile("ldmatrix.sync.aligned.m8n8.x4.shared.b16 {%0,%1,%2,%3}, [%4];"
                 : "=r"(r[0]), "=r"(r[1]), "=r"(r[2]), "=r"(r[3]) : "r"(a));
}
__device__ __forceinline__ void ldsm4t(uint32_t* r, uint32_t a) {
    asm volatile("ldmatrix.sync.aligned.m8n8.x4.trans.shared.b16 {%0,%1,%2,%3}, [%4];"
                 : "=r"(r[0]), "=r"(r[1]), "=r"(r[2]), "=r"(r[3]) : "r"(a));
}
__device__ __forceinline__ void mma_f16(float* c, const uint32_t* a,
                                        const uint32_t* b) {
    asm volatile(
        "mma.sync.aligned.m16n8k16.row.col.f32.f16.f16.f32 "
        "{%0,%1,%2,%3}, {%4,%5,%6,%7}, {%8,%9}, {%0,%1,%2,%3};"
        : "+f"(c[0]), "+f"(c[1]), "+f"(c[2]), "+f"(c[3])
        : "r"(a[0]), "r"(a[1]), "r"(a[2]), "r"(a[3]),
          "r"(b[0]), "r"(b[1]));
}
// swizzled byte offset: row r (64-half rows = 8 x 16B units), unit u
__device__ __forceinline__ uint32_t swz(int r, int u) {
    return (uint32_t)(((r << 3) + (u ^ (r & 7))) << 4);
}

// ---------------- merged weight transpose: all 6 weights in ONE launch -------
__global__ void __launch_bounds__(256) transpose_all(
    const float* __restrict__ Wq, const float* __restrict__ Wk,
    const float* __restrict__ Wv, const float* __restrict__ Wo,
    const float* __restrict__ W1, const float* __restrict__ W2,
    __half* __restrict__ wT) {
    __shared__ float t[32][33];
    int id = blockIdx.x;
    const float* src;
    __half* dst;
    int R, Ncols;
    if (id < 4096) {
        int seg = id >> 10;
        id &= 1023;
        src = (seg == 0) ? Wq : (seg == 1) ? Wk : (seg == 2) ? Wv : Wo;
        dst = wT + (size_t)seg * CC * CC;
        R = CC; Ncols = CC;
    } else if (id < 8192) {
        id -= 4096;
        src = W1; dst = wT + (size_t)4 * CC * CC;        // [WFF, CC]
        R = CC; Ncols = WFF;
    } else {
        id -= 8192;
        src = W2; dst = wT + (size_t)4 * CC * CC + (size_t)CC * WFF;  // [CC, WFF]
        R = WFF; Ncols = CC;
    }
    int txt = Ncols >> 5;
    int bx = (id % txt) << 5, by = (id / txt) << 5;
    int tx = threadIdx.x & 31, ty = threadIdx.x >> 5;
#pragma unroll
    for (int i = 0; i < 32; i += 8)
        t[ty + i][tx] = src[(size_t)(by + ty + i) * Ncols + bx + tx];
    __syncthreads();
#pragma unroll
    for (int i = 0; i < 32; i += 8)
        dst[(size_t)(bx + ty + i) * R + by + tx] = __float2half(t[tx][ty + i]);
}

// ---------------- concat QKV bias -------------------------------------------
__global__ void concat_bias(const float* __restrict__ a,
                            const float* __restrict__ b,
                            const float* __restrict__ c,
                            float* __restrict__ o) {
    int t = blockIdx.x * 256 + threadIdx.x;
    if (t < CC)            o[t] = a[t];
    else if (t < 2 * CC)   o[t] = b[t - CC];
    else if (t < 3 * CC)   o[t] = c[t - 2 * CC];
}

// ---------------- LayerNorm (fp32 in, fp16 out) ------------------------------
__global__ void __launch_bounds__(256) ln_kernel(
    const float* __restrict__ X, const float* __restrict__ gw,
    const float* __restrict__ gb, __half* __restrict__ O) {
    __shared__ float red[16];
    int row = blockIdx.x;
    int t = threadIdx.x;
    const float* xr = X + (size_t)row * CC;
    float4 v = *(const float4*)(xr + t * 4);
    float s  = v.x + v.y + v.z + v.w;
    float ss = v.x*v.x + v.y*v.y + v.z*v.z + v.w*v.w;
#pragma unroll
    for (int o = 16; o; o >>= 1) {
        s  += __shfl_down_sync(0xffffffffu, s,  o);
        ss += __shfl_down_sync(0xffffffffu, ss, o);
    }
    if ((t & 31) == 0) { red[t >> 5] = s; red[8 + (t >> 5)] = ss; }
    __syncthreads();
    if (t == 0) {
        float a = 0.f, c = 0.f;
#pragma unroll
        for (int i = 0; i < 8; i++) { a += red[i]; c += red[8 + i]; }
        float mean = a * (1.f / CC);
        float var  = c * (1.f / CC) - mean * mean;
        red[0] = mean;
        red[1] = rsqrtf(var + 1e-5f);
    }
    __syncthreads();
    float mean = red[0], rstd = red[1];
    float4 w4 = *(const float4*)(gw + t * 4);
    float4 b4 = *(const float4*)(gb + t * 4);
    __half2* op = (__half2*)(O + (size_t)row * CC);
    op[t * 2 + 0] = __floats2half2_rn((v.x - mean) * rstd * w4.x + b4.x,
                                      (v.y - mean) * rstd * w4.y + b4.y);
    op[t * 2 + 1] = __floats2half2_rn((v.z - mean) * rstd * w4.z + b4.z,
                                      (v.w - mean) * rstd * w4.w + b4.w);
}

// ---------------- persistent fp16 mma GEMM: tile 128x128, BK=64 --------------
// Grid = GRID_P CTAs; each walks tiles bx, bx+G, ... as ONE flat chunk stream.
// The 3-stage cp.async ring and 2-ahead prefetch cross tile boundaries, so
// next tile's loads overlap this tile's (smem-free) epilogue.
// EPI: 0 = bias -> fp16 out, 1 = bias+relu -> fp16 out, 2 = bias+residual -> fp32 out
#define GSMEM_BYTES (3 * 32768)   // 3 stages x (A 16KB + B 16KB)

template <int EPI>
__global__ void __launch_bounds__(256, 2) gemm_h(
    const __half* __restrict__ A, const __half* __restrict__ Bt,
    const float* __restrict__ bias, const float* __restrict__ res,
    void* __restrict__ Cout_, int M, int N, int K) {
    extern __shared__ char smc[];
    int tid = threadIdx.x, wid = tid >> 5, lane = tid & 31;
    int gid = lane >> 2, tig = lane & 3;
    int wm = wid >> 1, wn = wid & 1;
    uint32_t smb = smem_u32(smc);

    const int nbn   = N >> 7;
    const int nc    = K >> 6;
    const int ntile = (M >> 7) * nbn;
    const int G     = gridDim.x;
    const int bx    = blockIdx.x;
    if (bx >= ntile) return;
    const int myt = (ntile - bx + G - 1) / G;   // tiles owned by this CTA
    const int S   = myt * nc;                   // total chunks in my stream

    auto load_chunk = [&](int s) {
        int ti = s / nc;
        int t  = bx + ti * G;
        int c  = s - ti * nc;
        int bm = (t / nbn) << 7, bn = (t % nbn) << 7;
        const __half* Ac = A  + (size_t)bm * K + c * 64;
        const __half* Bc = Bt + (size_t)bn * K + c * 64;
        uint32_t ab = smb + (s % 3) * 32768;
        uint32_t bb = ab + 16384;
#pragma unroll
        for (int i = 0; i < 4; i++) {
            int idx = tid + (i << 8);
            int row = idx >> 3, u = idx & 7;
            uint32_t off = swz(row, u);
            cp16(ab + off, Ac + (size_t)row * K + (u << 3));
            cp16(bb + off, Bc + (size_t)row * K + (u << 3));
        }
    };

    float acc[2][8][4];
#pragma unroll
    for (int mt = 0; mt < 2; mt++)
#pragma unroll
        for (int nt = 0; nt < 8; nt++)
#pragma unroll
            for (int r = 0; r < 4; r++) acc[mt][nt][r] = 0.f;

    const int l15 = lane & 15, l7 = lane & 7;
    const int aU = lane >> 4;              // A unit add
    const int bR = (lane >> 4) << 3;       // B row add
    const int bU = (lane >> 3) & 1;        // B unit add

    load_chunk(0);
    CP_COMMIT();
    if (S > 1) { load_chunk(1); CP_COMMIT(); }

    for (int s = 0; s < S; s++) {
        if (s + 1 < S) CP_WAIT1(); else CP_WAIT0();
        __syncthreads();
        if (s + 2 < S) {
            load_chunk(s + 2);   // may belong to the NEXT tile: overlaps epilogue
            CP_COMMIT();
        }
        uint32_t sA = smb + (s % 3) * 32768;
        uint32_t sB = sA + 16384;
#pragma unroll
        for (int ks = 0; ks < 4; ks++) {
            uint32_t aF[2][4], bF[8][2];
#pragma unroll
            for (int mt = 0; mt < 2; mt++) {
                int r = wm * 32 + mt * 16 + l15;
                ldsm4(aF[mt], sA + swz(r, 2 * ks + aU));
            }
#pragma unroll
            for (int ntp = 0; ntp < 4; ntp++) {
                int r = wn * 64 + ntp * 16 + l7 + bR;
                uint32_t t4[4];
                ldsm4(t4, sB + swz(r, 2 * ks + bU));
                bF[2 * ntp][0] = t4[0]; bF[2 * ntp][1] = t4[1];
                bF[2 * ntp + 1][0] = t4[2]; bF[2 * ntp + 1][1] = t4[3];
            }
#pragma unroll
            for (int mt = 0; mt < 2; mt++)
#pragma unroll
                for (int nt = 0; nt < 8; nt++)
                    mma_f16(acc[mt][nt], aF[mt], bF[nt]);
        }

        // ---- tile complete: epilogue (registers -> global, no smem) ----
        if (s - (s / nc) * nc == nc - 1) {
            int t  = bx + (s / nc) * G;
            int bm = (t / nbn) << 7, bn = (t % nbn) << 7;
#pragma unroll
            for (int mt = 0; mt < 2; mt++) {
                int r0 = bm + wm * 32 + mt * 16 + gid;
#pragma unroll
                for (int half = 0; half < 2; half++) {
                    int row = r0 + half * 8;
#pragma unroll
                    for (int nt = 0; nt < 8; nt++) {
                        int col = bn + wn * 64 + nt * 8 + tig * 2;
                        float2 bv = *(const float2*)(bias + col);
                        float ox = acc[mt][nt][half * 2 + 0] + bv.x;
                        float oy = acc[mt][nt][half * 2 + 1] + bv.y;
                        if (EPI == 1) { ox = fmaxf(ox, 0.f); oy = fmaxf(oy, 0.f); }
                        if (EPI == 2) {
                            float2 rr = *(const float2*)(res + (size_t)row * N + col);
                            float* Co = (float*)Cout_;
                            *(float2*)(Co + (size_t)row * N + col) =
                                make_float2(ox + rr.x, oy + rr.y);
                        } else {
                            __half* Co = (__half*)Cout_;
                            *(__half2*)(Co + (size_t)row * N + col) =
                                __floats2half2_rn(ox, oy);
                        }
                    }
                }
            }
#pragma unroll
            for (int mt = 0; mt < 2; mt++)
#pragma unroll
                for (int nt = 0; nt < 8; nt++)
#pragma unroll
                    for (int r = 0; r < 4; r++) acc[mt][nt][r] = 0.f;
        }
    }
}

// ---------------- fp16 flash attention: BQ=128, BK=64, 3-buffer KV ring -----
// smem: sQ 16KB | sK 3x8KB | sV 3x8KB | sP 16KB  = 80KB
// Q pre-scaled by 0.125*log2(e): softmax runs in base-2 (exp2f).
#define AS_Q 0
#define AS_K 16384
#define AS_V 40960
#define AS_P 65536
#define ASMEM_BYTES 81920
#define QSCALE (0.125f * 1.4426950408889634f)

__global__ void __launch_bounds__(256) attn_h(
    const __half* __restrict__ QKV, __half* __restrict__ Y) {
    extern __shared__ char smc[];
    uint32_t smb = smem_u32(smc);
    // reversed mapping: heaviest (largest qt) tiles launch first -> better tail
    int qt = (gridDim.x - 1) - blockIdx.x;
    int hh = blockIdx.y, b = blockIdx.z;
    int tid = threadIdx.x, wid = tid >> 5, lane = tid & 31;
    int gid = lane >> 2, tig = lane & 3;
    int q0 = qt * 128;

    const __half* Qg = QKV + (size_t)b * TT * C3 + hh * DD;
    const __half* Kg = Qg + CC;
    const __half* Vg = Qg + 2 * CC;

    const int l15 = lane & 15, l7 = lane & 7;
    const int aU = lane >> 4;
    const int bR = (lane >> 4) << 3;
    const int bU = (lane >> 3) & 1;

    auto loadKV = [&](int t, int bf) {
        const __half* Kt = Kg + (size_t)(t * 64) * C3;
        const __half* Vt = Vg + (size_t)(t * 64) * C3;
        uint32_t dk = smb + AS_K + bf * 8192;
        uint32_t dv = smb + AS_V + bf * 8192;
#pragma unroll
        for (int i = 0; i < 2; i++) {
            int idx = tid + (i << 8);
            int row = idx >> 3, u = idx & 7;
            uint32_t off = swz(row, u);
            cp16(dk + off, Kt + (size_t)row * C3 + (u << 3));
            cp16(dv + off, Vt + (size_t)row * C3 + (u << 3));
        }
    };

    int ntiles = 2 * qt + 2;
    // Q tile: load via registers, scale by QSCALE, store swizzled fp16
    {
        const __half2 qs2 = __float2half2_rn(QSCALE);
#pragma unroll
        for (int i = 0; i < 4; i++) {
            int idx = tid + (i << 8);
            int row = idx >> 3, u = idx & 7;
            const __half2* src = (const __half2*)(Qg + (size_t)(q0 + row) * C3 + (u << 3));
            __half2 v0 = __hmul2(src[0], qs2);
            __half2 v1 = __hmul2(src[1], qs2);
            __half2 v2 = __hmul2(src[2], qs2);
            __half2 v3 = __hmul2(src[3], qs2);
            __half2* d = (__half2*)(smc + AS_Q + swz(row, u));
            d[0] = v0; d[1] = v1; d[2] = v2; d[3] = v3;
        }
    }
    loadKV(0, 0);
    CP_COMMIT();
    loadKV(1, 1);
    CP_COMMIT();
    CP_WAIT1();          // KV0 complete
    __syncthreads();

    // ---- Q fragments ----
    uint32_t qf[4][4];
#pragma unroll
    for (int ks = 0; ks < 4; ks++) {
        int r = wid * 16 + l15;
        ldsm4(qf[ks], smb + AS_Q + swz(r, 2 * ks + aU));
    }

    float m_i[2] = {-1e30f, -1e30f}, l_i[2] = {0.f, 0.f};
    float oacc[8][4];
#pragma unroll
    for (int nt = 0; nt < 8; nt++)
#pragma unroll
        for (int r = 0; r < 4; r++) oacc[nt][r] = 0.f;

    const int rbase = q0 + wid * 16 + gid;

    for (int t = 0; t < ntiles; t++) {
        if (t > 0) {
            if (t + 1 < ntiles) CP_WAIT1(); else CP_WAIT0();
            __syncthreads();
        }
        if (t + 2 < ntiles) {
            loadKV(t + 2, (t + 2) % 3);
            CP_COMMIT();
        }
        int k0t = t * 64;
        bool active = (k0t <= q0 + wid * 16 + 15);
        if (active) {
            int bf = t % 3;
            uint32_t sK = smb + AS_K + bf * 8192;
            uint32_t sV = smb + AS_V + bf * 8192;
            // ---- S' = (Q*scale*log2e) @ K^T ----
            float sfr[8][4];
#pragma unroll
            for (int nt = 0; nt < 8; nt++)
#pragma unroll
                for (int r = 0; r < 4; r++) sfr[nt][r] = 0.f;
#pragma unroll
            for (int ks = 0; ks < 4; ks++) {
                uint32_t bF[8][2];
#pragma unroll
                for (int ntp = 0; ntp < 4; ntp++) {
                    int r = ntp * 16 + l7 + bR;
                    uint32_t t4[4];
                    ldsm4(t4, sK + swz(r, 2 * ks + bU));
                    bF[2 * ntp][0] = t4[0]; bF[2 * ntp][1] = t4[1];
                    bF[2 * ntp + 1][0] = t4[2]; bF[2 * ntp + 1][1] = t4[3];
                }
#pragma unroll
                for (int nt = 0; nt < 8; nt++)
                    mma_f16(sfr[nt], qf[ks], bF[nt]);
            }
            // ---- causal mask ----
            if (k0t + 63 > rbase) {
#pragma unroll
                for (int nt = 0; nt < 8; nt++) {
                    int cb = k0t + nt * 8 + tig * 2;
                    if (cb     > rbase)     sfr[nt][0] = -1e30f;
                    if (cb + 1 > rbase)     sfr[nt][1] = -1e30f;
                    if (cb     > rbase + 8) sfr[nt][2] = -1e30f;
                    if (cb + 1 > rbase + 8) sfr[nt][3] = -1e30f;
                }
            }
            // ---- online softmax (base-2); write P (fp16) to per-warp smem --
#pragma unroll
            for (int h = 0; h < 2; h++) {
                float rm = -1e30f;
#pragma unroll
                for (int nt = 0; nt < 8; nt++)
                    rm = fmaxf(rm, fmaxf(sfr[nt][2 * h], sfr[nt][2 * h + 1]));
                rm = fmaxf(rm, __shfl_xor_sync(0xffffffffu, rm, 1));
                rm = fmaxf(rm, __shfl_xor_sync(0xffffffffu, rm, 2));
                float mn = fmaxf(m_i[h], rm);
                float alpha = exp2f(m_i[h] - mn);
                m_i[h] = mn;
                float rs = 0.f;
                int pr = wid * 16 + gid + h * 8;
#pragma unroll
                for (int nt = 0; nt < 8; nt++) {
                    float p0 = exp2f(sfr[nt][2 * h]     - mn);
                    float p1 = exp2f(sfr[nt][2 * h + 1] - mn);
                    rs += p0 + p1;
                    int col = nt * 8 + tig * 2;
                    *(__half2*)(smc + AS_P + swz(pr, col >> 3) + (col & 7) * 2) =
                        __floats2half2_rn(p0, p1);
                    oacc[nt][2 * h]     *= alpha;
                    oacc[nt][2 * h + 1] *= alpha;
                }
                rs += __shfl_xor_sync(0xffffffffu, rs, 1);
                rs += __shfl_xor_sync(0xffffffffu, rs, 2);
                l_i[h] = l_i[h] * alpha + rs;
            }
            __syncwarp();
            // ---- O += P @ V  (V via ldmatrix.trans) ----
#pragma unroll
            for (int ks = 0; ks < 4; ks++) {
                uint32_t pf[4];
                {
                    int r = wid * 16 + l15;
                    ldsm4(pf, smb + AS_P + swz(r, 2 * ks + aU));
                }
#pragma unroll
                for (int ntp = 0; ntp < 4; ntp++) {
                    int kk = ks * 16 + l7 + ((lane >> 3) & 1) * 8;
                    uint32_t t4[4];
                    ldsm4t(t4, sV + swz(kk, 2 * ntp + aU));
                    mma_f16(oacc[2 * ntp],     pf, t4);
                    mma_f16(oacc[2 * ntp + 1], pf, t4 + 2);
                }
            }
        }
    }

    // ---- output (fp16, feeds Wo GEMM) ----
    __half* Yg = Y + (size_t)b * TT * CC + hh * DD;
#pragma unroll
    for (int h = 0; h < 2; h++) {
        float inv = 1.f / l_i[h];
        __half* yr = Yg + (size_t)(rbase + h * 8) * CC;
#pragma unroll
        for (int nt = 0; nt < 8; nt++) {
            int col = nt * 8 + tig * 2;
            *(__half2*)(yr + col) = __floats2half2_rn(
                oacc[nt][2 * h] * inv, oacc[nt][2 * h + 1] * inv);
        }
    }
}

// ---------------- launch ---------------------------------------------------
extern "C" void kernel_launch(void* const* d_in, const int* in_sizes, int n_in,
                              void* d_out, int out_size) {
    const float* x    = (const float*)d_in[0];
    const float* ln1w = (const float*)d_in[1];
    const float* ln1b = (const float*)d_in[2];
    const float* Wq   = (const float*)d_in[3];
    const float* bq   = (const float*)d_in[4];
    const float* Wk   = (const float*)d_in[5];
    const float* bk   = (const float*)d_in[6];
    const float* Wv   = (const float*)d_in[7];
    const float* bv   = (const float*)d_in[8];
    const float* Wo   = (const float*)d_in[9];
    const float* bo   = (const float*)d_in[10];
    const float* ln2w = (const float*)d_in[11];
    const float* ln2b = (const float*)d_in[12];
    const float* W1   = (const float*)d_in[13];
    const float* b1   = (const float*)d_in[14];
    const float* W2   = (const float*)d_in[15];
    const float* b2   = (const float*)d_in[16];
    float* out = (float*)d_out;

    __half *h, *qkv, *y, *ff, *wT;
    float *x2, *bqkv;
    cudaGetSymbolAddress((void**)&h,    g_h);
    cudaGetSymbolAddress((void**)&qkv,  g_qkv);
    cudaGetSymbolAddress((void**)&y,    g_y);
    cudaGetSymbolAddress((void**)&x2,   g_x2);
    cudaGetSymbolAddress((void**)&ff,   g_ff);
    cudaGetSymbolAddress((void**)&wT,   g_wT);
    cudaGetSymbolAddress((void**)&bqkv, g_bqkv);

    __half* WqkvT = wT;                                  // [3C, C]
    __half* WoT   = WqkvT + (size_t)3 * CC * CC;         // [C, C]
    __half* W1T   = WoT + (size_t)CC * CC;               // [WFF, C]
    __half* W2T   = W1T + (size_t)CC * WFF;              // [C, WFF]

    cudaFuncSetAttribute(attn_h,
                         cudaFuncAttributeMaxDynamicSharedMemorySize, ASMEM_BYTES);
    cudaFuncSetAttribute(gemm_h<0>,
                         cudaFuncAttributeMaxDynamicSharedMemorySize, GSMEM_BYTES);
    cudaFuncSetAttribute(gemm_h<1>,
                         cudaFuncAttributeMaxDynamicSharedMemorySize, GSMEM_BYTES);
    cudaFuncSetAttribute(gemm_h<2>,
                         cudaFuncAttributeMaxDynamicSharedMemorySize, GSMEM_BYTES);

    // ---- merged weight transpose (1 launch) + bias concat ----
    transpose_all<<<12288, 256>>>(Wq, Wk, Wv, Wo, W1, W2, wT);
    concat_bias<<<12, 256>>>(bq, bk, bv, bqkv);

    // LN1
    ln_kernel<<<MM, 256>>>(x, ln1w, ln1b, h);
    // fused QKV projection (N = 3072), persistent grid
    gemm_h<0><<<GRID_P, 256, GSMEM_BYTES>>>(h, WqkvT, bqkv, nullptr, qkv, MM, C3, CC);
    // causal attention
    attn_h<<<dim3(TT / 128, HH, BB), 256, ASMEM_BYTES>>>(qkv, y);
    // output projection + residual
    gemm_h<2><<<GRID_P, 256, GSMEM_BYTES>>>(y, WoT, bo, x, x2, MM, CC, CC);
    // LN2
    ln_kernel<<<MM, 256>>>(x2, ln2w, ln2b, h);
    // FF1 (relu)
    gemm_h<1><<<GRID_P, 256, GSMEM_BYTES>>>(h, W1T, b1, nullptr, ff, MM, WFF, CC);
    // FF2 + residual -> out
    gemm_h<2><<<GRID_P, 256, GSMEM_BYTES>>>(ff, W2T, b2, x2, out, MM, CC, WFF);
}

// round 12
// speedup vs baseline: 1.0809x; 1.0809x over previous
#include <cuda_runtime.h>
#include <cuda_fp16.h>
#include <cstdint>
#include <math.h>

#define BB  4
#define TT  2048
#define CC  1024
#define HH  16
#define DD  64
#define WFF 4096
#define MM  (BB*TT)   // 8192
#define C3  (3*CC)    // 3072
#define GRID_P 296    // 148 SMs x 2 CTAs

// ---------------- scratch (device globals: allocation-free) ----------------
__device__ __half g_h  [(size_t)MM*CC];
__device__ __half g_qkv[(size_t)MM*C3];
__device__ __half g_y  [(size_t)MM*CC];
__device__ float  g_x2 [(size_t)MM*CC];
__device__ __half g_ff [(size_t)MM*WFF];
__device__ __half g_wT [(size_t)4*CC*CC + (size_t)2*CC*WFF];
__device__ float  g_bqkv[C3];

// ---------------- helpers ----------------------------------------------------
__device__ __forceinline__ uint32_t smem_u32(const void* p) {
    uint32_t a;
    asm("{ .reg .u64 t; cvta.to.shared.u64 t, %1; cvt.u32.u64 %0, t; }"
        : "=r"(a) : "l"(p));
    return a;
}
__device__ __forceinline__ void cp16(uint32_t s, const void* g) {
    asm volatile("cp.async.cg.shared.global [%0], [%1], 16;"
                 :: "r"(s), "l"(g) : "memory");
}
#define CP_COMMIT() asm volatile("cp.async.commit_group;" ::: "memory")
#define CP_WAIT0()  asm volatile("cp.async.wait_group 0;" ::: "memory")
#define CP_WAIT1()  asm volatile("cp.async.wait_group 1;" ::: "memory")

__device__ __forceinline__ void ldsm4(uint32_t* r, uint32_t a) {
    asm volatile("ldmatrix.sync.aligned.m8n8.x4.shared.b16 {%0,%1,%2,%3}, [%4];"
                 : "=r"(r[0]), "=r"(r[1]), "=r"(r[2]), "=r"(r[3]) : "r"(a));
}
__device__ __forceinline__ void ldsm4t(uint32_t* r, uint32_t a) {
    asm volatile("ldmatrix.sync.aligned.m8n8.x4.trans.shared.b16 {%0,%1,%2,%3}, [%4];"
                 : "=r"(r[0]), "=r"(r[1]), "=r"(r[2]), "=r"(r[3]) : "r"(a));
}
__device__ __forceinline__ void mma_f16(float* c, const uint32_t* a,
                                        const uint32_t* b) {
    asm volatile(
        "mma.sync.aligned.m16n8k16.row.col.f32.f16.f16.f32 "
        "{%0,%1,%2,%3}, {%4,%5,%6,%7}, {%8,%9}, {%0,%1,%2,%3};"
        : "+f"(c[0]), "+f"(c[1]), "+f"(c[2]), "+f"(c[3])
        : "r"(a[0]), "r"(a[1]), "r"(a[2]), "r"(a[3]),
          "r"(b[0]), "r"(b[1]));
}
// swizzled byte offset: row r (64-half rows = 8 x 16B units), unit u
__device__ __forceinline__ uint32_t swz(int r, int u) {
    return (uint32_t)(((r << 3) + (u ^ (r & 7))) << 4);
}

// ---------------- merged weight transpose: all 6 weights in ONE launch -------
__global__ void __launch_bounds__(256) transpose_all(
    const float* __restrict__ Wq, const float* __restrict__ Wk,
    const float* __restrict__ Wv, const float* __restrict__ Wo,
    const float* __restrict__ W1, const float* __restrict__ W2,
    __half* __restrict__ wT) {
    __shared__ float t[32][33];
    int id = blockIdx.x;
    const float* src;
    __half* dst;
    int R, Ncols;
    if (id < 4096) {
        int seg = id >> 10;
        id &= 1023;
        src = (seg == 0) ? Wq : (seg == 1) ? Wk : (seg == 2) ? Wv : Wo;
        dst = wT + (size_t)seg * CC * CC;
        R = CC; Ncols = CC;
    } else if (id < 8192) {
        id -= 4096;
        src = W1; dst = wT + (size_t)4 * CC * CC;        // [WFF, CC]
        R = CC; Ncols = WFF;
    } else {
        id -= 8192;
        src = W2; dst = wT + (size_t)4 * CC * CC + (size_t)CC * WFF;  // [CC, WFF]
        R = WFF; Ncols = CC;
    }
    int txt = Ncols >> 5;
    int bx = (id % txt) << 5, by = (id / txt) << 5;
    int tx = threadIdx.x & 31, ty = threadIdx.x >> 5;
#pragma unroll
    for (int i = 0; i < 32; i += 8)
        t[ty + i][tx] = src[(size_t)(by + ty + i) * Ncols + bx + tx];
    __syncthreads();
#pragma unroll
    for (int i = 0; i < 32; i += 8)
        dst[(size_t)(bx + ty + i) * R + by + tx] = __float2half(t[tx][ty + i]);
}

// ---------------- concat QKV bias -------------------------------------------
__global__ void concat_bias(const float* __restrict__ a,
                            const float* __restrict__ b,
                            const float* __restrict__ c,
                            float* __restrict__ o) {
    int t = blockIdx.x * 256 + threadIdx.x;
    if (t < CC)            o[t] = a[t];
    else if (t < 2 * CC)   o[t] = b[t - CC];
    else if (t < 3 * CC)   o[t] = c[t - 2 * CC];
}

// ---------------- LayerNorm (fp32 in, fp16 out) ------------------------------
__global__ void __launch_bounds__(256) ln_kernel(
    const float* __restrict__ X, const float* __restrict__ gw,
    const float* __restrict__ gb, __half* __restrict__ O) {
    __shared__ float red[16];
    int row = blockIdx.x;
    int t = threadIdx.x;
    const float* xr = X + (size_t)row * CC;
    float4 v = *(const float4*)(xr + t * 4);
    float s  = v.x + v.y + v.z + v.w;
    float ss = v.x*v.x + v.y*v.y + v.z*v.z + v.w*v.w;
#pragma unroll
    for (int o = 16; o; o >>= 1) {
        s  += __shfl_down_sync(0xffffffffu, s,  o);
        ss += __shfl_down_sync(0xffffffffu, ss, o);
    }
    if ((t & 31) == 0) { red[t >> 5] = s; red[8 + (t >> 5)] = ss; }
    __syncthreads();
    if (t == 0) {
        float a = 0.f, c = 0.f;
#pragma unroll
        for (int i = 0; i < 8; i++) { a += red[i]; c += red[8 + i]; }
        float mean = a * (1.f / CC);
        float var  = c * (1.f / CC) - mean * mean;
        red[0] = mean;
        red[1] = rsqrtf(var + 1e-5f);
    }
    __syncthreads();
    float mean = red[0], rstd = red[1];
    float4 w4 = *(const float4*)(gw + t * 4);
    float4 b4 = *(const float4*)(gb + t * 4);
    __half2* op = (__half2*)(O + (size_t)row * CC);
    op[t * 2 + 0] = __floats2half2_rn((v.x - mean) * rstd * w4.x + b4.x,
                                      (v.y - mean) * rstd * w4.y + b4.y);
    op[t * 2 + 1] = __floats2half2_rn((v.z - mean) * rstd * w4.z + b4.z,
                                      (v.w - mean) * rstd * w4.w + b4.w);
}

// ---------------- persistent fp16 mma GEMM v2: division-free cursors ---------
// Grid = GRID_P CTAs; each walks its tiles as one flat chunk stream with the
// 3-stage cp.async ring crossing tile boundaries (prefetch hides epilogue).
// All per-chunk indexing is increment-and-wrap; tile-base divisions happen
// once per TILE (amortized over nc chunks).
// EPI: 0 = bias -> fp16 out, 1 = bias+relu -> fp16 out, 2 = bias+residual -> fp32 out
#define GSMEM_BYTES (3 * 32768)   // 3 stages x (A 16KB + B 16KB)

template <int EPI>
__global__ void __launch_bounds__(256, 2) gemm_h(
    const __half* __restrict__ A, const __half* __restrict__ Bt,
    const float* __restrict__ bias, const float* __restrict__ res,
    void* __restrict__ Cout_, int M, int N, int K) {
    extern __shared__ char smc[];
    int tid = threadIdx.x, wid = tid >> 5, lane = tid & 31;
    int gid = lane >> 2, tig = lane & 3;
    int wm = wid >> 1, wn = wid & 1;
    uint32_t smb = smem_u32(smc);

    const int nbn   = N >> 7;
    const int nc    = K >> 6;
    const int ntile = (M >> 7) * nbn;
    const int G     = gridDim.x;
    const int bx    = blockIdx.x;
    if (bx >= ntile) return;
    const int S = ((ntile - bx + G - 1) / G) * nc;   // my total chunk count

    // ---- load cursor (division once per tile) ----
    int lt = bx, lc = 0, ls = 0;
    const __half* lA = A  + (size_t)((lt / nbn) << 7) * K;
    const __half* lB = Bt + (size_t)((lt % nbn) << 7) * K;

    auto load_next = [&]() {
        const __half* Ac = lA + lc * 64;
        const __half* Bc = lB + lc * 64;
        uint32_t ab = smb + ls * 32768;
        uint32_t bb = ab + 16384;
#pragma unroll
        for (int i = 0; i < 4; i++) {
            int idx = tid + (i << 8);
            int row = idx >> 3, u = idx & 7;
            uint32_t off = swz(row, u);
            cp16(ab + off, Ac + (size_t)row * K + (u << 3));
            cp16(bb + off, Bc + (size_t)row * K + (u << 3));
        }
        CP_COMMIT();
        if (++ls == 3) ls = 0;
        if (++lc == nc) {
            lc = 0;
            lt += G;
            if (lt < ntile) {
                lA = A  + (size_t)((lt / nbn) << 7) * K;
                lB = Bt + (size_t)((lt % nbn) << 7) * K;
            }
        }
    };

    float acc[2][8][4];
#pragma unroll
    for (int mt = 0; mt < 2; mt++)
#pragma unroll
        for (int nt = 0; nt < 8; nt++)
#pragma unroll
            for (int r = 0; r < 4; r++) acc[mt][nt][r] = 0.f;

    const int l15 = lane & 15, l7 = lane & 7;
    const int aU = lane >> 4;              // A unit add
    const int bR = (lane >> 4) << 3;       // B row add
    const int bU = (lane >> 3) & 1;        // B unit add

    load_next();
    if (S > 1) load_next();

    // ---- compute cursor ----
    int ct = bx, cc = 0, cs = 0;
    int cbm = (ct / nbn) << 7, cbn = (ct % nbn) << 7;

    for (int s = 0; s < S; s++) {
        if (s + 1 < S) CP_WAIT1(); else CP_WAIT0();
        __syncthreads();
        if (s + 2 < S) load_next();     // may cross into next tile
        uint32_t sA = smb + cs * 32768;
        uint32_t sB = sA + 16384;
#pragma unroll
        for (int ks = 0; ks < 4; ks++) {
            uint32_t aF[2][4], bF[8][2];
#pragma unroll
            for (int mt = 0; mt < 2; mt++) {
                int r = wm * 32 + mt * 16 + l15;
                ldsm4(aF[mt], sA + swz(r, 2 * ks + aU));
            }
#pragma unroll
            for (int ntp = 0; ntp < 4; ntp++) {
                int r = wn * 64 + ntp * 16 + l7 + bR;
                uint32_t t4[4];
                ldsm4(t4, sB + swz(r, 2 * ks + bU));
                bF[2 * ntp][0] = t4[0]; bF[2 * ntp][1] = t4[1];
                bF[2 * ntp + 1][0] = t4[2]; bF[2 * ntp + 1][1] = t4[3];
            }
#pragma unroll
            for (int mt = 0; mt < 2; mt++)
#pragma unroll
                for (int nt = 0; nt < 8; nt++)
                    mma_f16(acc[mt][nt], aF[mt], bF[nt]);
        }
        if (++cs == 3) cs = 0;

        if (++cc == nc) {
            // ---- tile complete: epilogue (registers -> global, no smem) ----
#pragma unroll
            for (int mt = 0; mt < 2; mt++) {
                int r0 = cbm + wm * 32 + mt * 16 + gid;
#pragma unroll
                for (int half = 0; half < 2; half++) {
                    int row = r0 + half * 8;
#pragma unroll
                    for (int nt = 0; nt < 8; nt++) {
                        int col = cbn + wn * 64 + nt * 8 + tig * 2;
                        float2 bv = *(const float2*)(bias + col);
                        float ox = acc[mt][nt][half * 2 + 0] + bv.x;
                        float oy = acc[mt][nt][half * 2 + 1] + bv.y;
                        if (EPI == 1) { ox = fmaxf(ox, 0.f); oy = fmaxf(oy, 0.f); }
                        if (EPI == 2) {
                            float2 rr = *(const float2*)(res + (size_t)row * N + col);
                            float* Co = (float*)Cout_;
                            *(float2*)(Co + (size_t)row * N + col) =
                                make_float2(ox + rr.x, oy + rr.y);
                        } else {
                            __half* Co = (__half*)Cout_;
                            *(__half2*)(Co + (size_t)row * N + col) =
                                __floats2half2_rn(ox, oy);
                        }
                    }
                }
            }
#pragma unroll
            for (int mt = 0; mt < 2; mt++)
#pragma unroll
                for (int nt = 0; nt < 8; nt++)
#pragma unroll
                    for (int r = 0; r < 4; r++) acc[mt][nt][r] = 0.f;
            cc = 0;
            ct += G;
            if (ct < ntile) {
                cbm = (ct / nbn) << 7;
                cbn = (ct % nbn) << 7;
            }
        }
    }
}

// ---------------- fp16 flash attention: BQ=128, BK=64, 3-buffer KV ring -----
// smem: sQ 16KB | sK 3x8KB | sV 3x8KB | sP 16KB  = 80KB
// Q pre-scaled by 0.125*log2(e): softmax runs in base-2 (exp2f).
#define AS_Q 0
#define AS_K 16384
#define AS_V 40960
#define AS_P 65536
#define ASMEM_BYTES 81920
#define QSCALE (0.125f * 1.4426950408889634f)

__global__ void __launch_bounds__(256) attn_h(
    const __half* __restrict__ QKV, __half* __restrict__ Y) {
    extern __shared__ char smc[];
    uint32_t smb = smem_u32(smc);
    // reversed mapping: heaviest (largest qt) tiles launch first -> better tail
    int qt = (gridDim.x - 1) - blockIdx.x;
    int hh = blockIdx.y, b = blockIdx.z;
    int tid = threadIdx.x, wid = tid >> 5, lane = tid & 31;
    int gid = lane >> 2, tig = lane & 3;
    int q0 = qt * 128;

    const __half* Qg = QKV + (size_t)b * TT * C3 + hh * DD;
    const __half* Kg = Qg + CC;
    const __half* Vg = Qg + 2 * CC;

    const int l15 = lane & 15, l7 = lane & 7;
    const int aU = lane >> 4;
    const int bR = (lane >> 4) << 3;
    const int bU = (lane >> 3) & 1;

    auto loadKV = [&](int t, int bf) {
        const __half* Kt = Kg + (size_t)(t * 64) * C3;
        const __half* Vt = Vg + (size_t)(t * 64) * C3;
        uint32_t dk = smb + AS_K + bf * 8192;
        uint32_t dv = smb + AS_V + bf * 8192;
#pragma unroll
        for (int i = 0; i < 2; i++) {
            int idx = tid + (i << 8);
            int row = idx >> 3, u = idx & 7;
            uint32_t off = swz(row, u);
            cp16(dk + off, Kt + (size_t)row * C3 + (u << 3));
            cp16(dv + off, Vt + (size_t)row * C3 + (u << 3));
        }
    };

    int ntiles = 2 * qt + 2;
    // Q tile: load via registers, scale by QSCALE, store swizzled fp16
    {
        const __half2 qs2 = __float2half2_rn(QSCALE);
#pragma unroll
        for (int i = 0; i < 4; i++) {
            int idx = tid + (i << 8);
            int row = idx >> 3, u = idx & 7;
            const __half2* src = (const __half2*)(Qg + (size_t)(q0 + row) * C3 + (u << 3));
            __half2 v0 = __hmul2(src[0], qs2);
            __half2 v1 = __hmul2(src[1], qs2);
            __half2 v2 = __hmul2(src[2], qs2);
            __half2 v3 = __hmul2(src[3], qs2);
            __half2* d = (__half2*)(smc + AS_Q + swz(row, u));
            d[0] = v0; d[1] = v1; d[2] = v2; d[3] = v3;
        }
    }
    loadKV(0, 0);
    CP_COMMIT();
    loadKV(1, 1);
    CP_COMMIT();
    CP_WAIT1();          // KV0 complete
    __syncthreads();

    // ---- Q fragments ----
    uint32_t qf[4][4];
#pragma unroll
    for (int ks = 0; ks < 4; ks++) {
        int r = wid * 16 + l15;
        ldsm4(qf[ks], smb + AS_Q + swz(r, 2 * ks + aU));
    }

    float m_i[2] = {-1e30f, -1e30f}, l_i[2] = {0.f, 0.f};
    float oacc[8][4];
#pragma unroll
    for (int nt = 0; nt < 8; nt++)
#pragma unroll
        for (int r = 0; r < 4; r++) oacc[nt][r] = 0.f;

    const int rbase = q0 + wid * 16 + gid;

    for (int t = 0; t < ntiles; t++) {
        if (t > 0) {
            if (t + 1 < ntiles) CP_WAIT1(); else CP_WAIT0();
            __syncthreads();
        }
        if (t + 2 < ntiles) {
            loadKV(t + 2, (t + 2) % 3);
            CP_COMMIT();
        }
        int k0t = t * 64;
        bool active = (k0t <= q0 + wid * 16 + 15);
        if (active) {
            int bf = t % 3;
            uint32_t sK = smb + AS_K + bf * 8192;
            uint32_t sV = smb + AS_V + bf * 8192;
            // ---- S' = (Q*scale*log2e) @ K^T ----
            float sfr[8][4];
#pragma unroll
            for (int nt = 0; nt < 8; nt++)
#pragma unroll
                for (int r = 0; r < 4; r++) sfr[nt][r] = 0.f;
#pragma unroll
            for (int ks = 0; ks < 4; ks++) {
                uint32_t bF[8][2];
#pragma unroll
                for (int ntp = 0; ntp < 4; ntp++) {
                    int r = ntp * 16 + l7 + bR;
                    uint32_t t4[4];
                    ldsm4(t4, sK + swz(r, 2 * ks + bU));
                    bF[2 * ntp][0] = t4[0]; bF[2 * ntp][1] = t4[1];
                    bF[2 * ntp + 1][0] = t4[2]; bF[2 * ntp + 1][1] = t4[3];
                }
#pragma unroll
                for (int nt = 0; nt < 8; nt++)
                    mma_f16(sfr[nt], qf[ks], bF[nt]);
            }
            // ---- causal mask ----
            if (k0t + 63 > rbase) {
#pragma unroll
                for (int nt = 0; nt < 8; nt++) {
                    int cb = k0t + nt * 8 + tig * 2;
                    if (cb     > rbase)     sfr[nt][0] = -1e30f;
                    if (cb + 1 > rbase)     sfr[nt][1] = -1e30f;
                    if (cb     > rbase + 8) sfr[nt][2] = -1e30f;
                    if (cb + 1 > rbase + 8) sfr[nt][3] = -1e30f;
                }
            }
            // ---- online softmax (base-2); write P (fp16) to per-warp smem --
#pragma unroll
            for (int h = 0; h < 2; h++) {
                float rm = -1e30f;
#pragma unroll
                for (int nt = 0; nt < 8; nt++)
                    rm = fmaxf(rm, fmaxf(sfr[nt][2 * h], sfr[nt][2 * h + 1]));
                rm = fmaxf(rm, __shfl_xor_sync(0xffffffffu, rm, 1));
                rm = fmaxf(rm, __shfl_xor_sync(0xffffffffu, rm, 2));
                float mn = fmaxf(m_i[h], rm);
                float alpha = exp2f(m_i[h] - mn);
                m_i[h] = mn;
                float rs = 0.f;
                int pr = wid * 16 + gid + h * 8;
#pragma unroll
                for (int nt = 0; nt < 8; nt++) {
                    float p0 = exp2f(sfr[nt][2 * h]     - mn);
                    float p1 = exp2f(sfr[nt][2 * h + 1] - mn);
                    rs += p0 + p1;
                    int col = nt * 8 + tig * 2;
                    *(__half2*)(smc + AS_P + swz(pr, col >> 3) + (col & 7) * 2) =
                        __floats2half2_rn(p0, p1);
                    oacc[nt][2 * h]     *= alpha;
                    oacc[nt][2 * h + 1] *= alpha;
                }
                rs += __shfl_xor_sync(0xffffffffu, rs, 1);
                rs += __shfl_xor_sync(0xffffffffu, rs, 2);
                l_i[h] = l_i[h] * alpha + rs;
            }
            __syncwarp();
            // ---- O += P @ V  (V via ldmatrix.trans) ----
#pragma unroll
            for (int ks = 0; ks < 4; ks++) {
                uint32_t pf[4];
                {
                    int r = wid * 16 + l15;
                    ldsm4(pf, smb + AS_P + swz(r, 2 * ks + aU));
                }
#pragma unroll
                for (int ntp = 0; ntp < 4; ntp++) {
                    int kk = ks * 16 + l7 + ((lane >> 3) & 1) * 8;
                    uint32_t t4[4];
                    ldsm4t(t4, sV + swz(kk, 2 * ntp + aU));
                    mma_f16(oacc[2 * ntp],     pf, t4);
                    mma_f16(oacc[2 * ntp + 1], pf, t4 + 2);
                }
            }
        }
    }

    // ---- output (fp16, feeds Wo GEMM) ----
    __half* Yg = Y + (size_t)b * TT * CC + hh * DD;
#pragma unroll
    for (int h = 0; h < 2; h++) {
        float inv = 1.f / l_i[h];
        __half* yr = Yg + (size_t)(rbase + h * 8) * CC;
#pragma unroll
        for (int nt = 0; nt < 8; nt++) {
            int col = nt * 8 + tig * 2;
            *(__half2*)(yr + col) = __floats2half2_rn(
                oacc[nt][2 * h] * inv, oacc[nt][2 * h + 1] * inv);
        }
    }
}

// ---------------- launch ---------------------------------------------------
extern "C" void kernel_launch(void* const* d_in, const int* in_sizes, int n_in,
                              void* d_out, int out_size) {
    const float* x    = (const float*)d_in[0];
    const float* ln1w = (const float*)d_in[1];
    const float* ln1b = (const float*)d_in[2];
    const float* Wq   = (const float*)d_in[3];
    const float* bq   = (const float*)d_in[4];
    const float* Wk   = (const float*)d_in[5];
    const float* bk   = (const float*)d_in[6];
    const float* Wv   = (const float*)d_in[7];
    const float* bv   = (const float*)d_in[8];
    const float* Wo   = (const float*)d_in[9];
    const float* bo   = (const float*)d_in[10];
    const float* ln2w = (const float*)d_in[11];
    const float* ln2b = (const float*)d_in[12];
    const float* W1   = (const float*)d_in[13];
    const float* b1   = (const float*)d_in[14];
    const float* W2   = (const float*)d_in[15];
    const float* b2   = (const float*)d_in[16];
    float* out = (float*)d_out;

    __half *h, *qkv, *y, *ff, *wT;
    float *x2, *bqkv;
    cudaGetSymbolAddress((void**)&h,    g_h);
    cudaGetSymbolAddress((void**)&qkv,  g_qkv);
    cudaGetSymbolAddress((void**)&y,    g_y);
    cudaGetSymbolAddress((void**)&x2,   g_x2);
    cudaGetSymbolAddress((void**)&ff,   g_ff);
    cudaGetSymbolAddress((void**)&wT,   g_wT);
    cudaGetSymbolAddress((void**)&bqkv, g_bqkv);

    __half* WqkvT = wT;                                  // [3C, C]
    __half* WoT   = WqkvT + (size_t)3 * CC * CC;         // [C, C]
    __half* W1T   = WoT + (size_t)CC * CC;               // [WFF, C]
    __half* W2T   = W1T + (size_t)CC * WFF;              // [C, WFF]

    cudaFuncSetAttribute(attn_h,
                         cudaFuncAttributeMaxDynamicSharedMemorySize, ASMEM_BYTES);
    cudaFuncSetAttribute(gemm_h<0>,
                         cudaFuncAttributeMaxDynamicSharedMemorySize, GSMEM_BYTES);
    cudaFuncSetAttribute(gemm_h<1>,
                         cudaFuncAttributeMaxDynamicSharedMemorySize, GSMEM_BYTES);
    cudaFuncSetAttribute(gemm_h<2>,
                         cudaFuncAttributeMaxDynamicSharedMemorySize, GSMEM_BYTES);

    // ---- merged weight transpose (1 launch) + bias concat ----
    transpose_all<<<12288, 256>>>(Wq, Wk, Wv, Wo, W1, W2, wT);
    concat_bias<<<12, 256>>>(bq, bk, bv, bqkv);

    // LN1
    ln_kernel<<<MM, 256>>>(x, ln1w, ln1b, h);
    // fused QKV projection (N = 3072), persistent grid
    gemm_h<0><<<GRID_P, 256, GSMEM_BYTES>>>(h, WqkvT, bqkv, nullptr, qkv, MM, C3, CC);
    // causal attention
    attn_h<<<dim3(TT / 128, HH, BB), 256, ASMEM_BYTES>>>(qkv, y);
    // output projection + residual
    gemm_h<2><<<GRID_P, 256, GSMEM_BYTES>>>(y, WoT, bo, x, x2, MM, CC, CC);
    // LN2
    ln_kernel<<<MM, 256>>>(x2, ln2w, ln2b, h);
    // FF1 (relu)
    gemm_h<1><<<GRID_P, 256, GSMEM_BYTES>>>(h, W1T, b1, nullptr, ff, MM, WFF, CC);
    // FF2 + residual -> out
    gemm_h<2><<<GRID_P, 256, GSMEM_BYTES>>>(ff, W2T, b2, x2, out, MM, CC, WFF);
}

// round 13
// speedup vs baseline: 1.1473x; 1.0614x over previous
#include <cuda_runtime.h>
#include <cuda_fp16.h>
#include <cstdint>
#include <math.h>

#define BB  4
#define TT  2048
#define CC  1024
#define HH  16
#define DD  64
#define WFF 4096
#define MM  (BB*TT)   // 8192
#define C3  (3*CC)    // 3072

// ---------------- scratch (device globals: allocation-free) ----------------
__device__ __half g_h  [(size_t)MM*CC];
__device__ __half g_qkv[(size_t)MM*C3];
__device__ __half g_y  [(size_t)MM*CC];
__device__ __half g_x2 [(size_t)MM*CC];     // fp16 residual trunk
__device__ __half g_ff [(size_t)MM*WFF];
__device__ __half g_wT [(size_t)4*CC*CC + (size_t)2*CC*WFF];
__device__ float  g_bqkv[C3];

// ---------------- helpers ----------------------------------------------------
__device__ __forceinline__ uint32_t smem_u32(const void* p) {
    uint32_t a;
    asm("{ .reg .u64 t; cvta.to.shared.u64 t, %1; cvt.u32.u64 %0, t; }"
        : "=r"(a) : "l"(p));
    return a;
}
__device__ __forceinline__ void cp16(uint32_t s, const void* g) {
    asm volatile("cp.async.cg.shared.global [%0], [%1], 16;"
                 :: "r"(s), "l"(g) : "memory");
}
#define CP_COMMIT() asm volatile("cp.async.commit_group;" ::: "memory")
#define CP_WAIT0()  asm volatile("cp.async.wait_group 0;" ::: "memory")
#define CP_WAIT1()  asm volatile("cp.async.wait_group 1;" ::: "memory")

__device__ __forceinline__ void ldsm4(uint32_t* r, uint32_t a) {
    asm volatile("ldmatrix.sync.aligned.m8n8.x4.shared.b16 {%0,%1,%2,%3}, [%4];"
                 : "=r"(r[0]), "=r"(r[1]), "=r"(r[2]), "=r"(r[3]) : "r"(a));
}
__device__ __forceinline__ void ldsm4t(uint32_t* r, uint32_t a) {
    asm volatile("ldmatrix.sync.aligned.m8n8.x4.trans.shared.b16 {%0,%1,%2,%3}, [%4];"
                 : "=r"(r[0]), "=r"(r[1]), "=r"(r[2]), "=r"(r[3]) : "r"(a));
}
__device__ __forceinline__ void mma_f16(float* c, const uint32_t* a,
                                        const uint32_t* b) {
    asm volatile(
        "mma.sync.aligned.m16n8k16.row.col.f32.f16.f16.f32 "
        "{%0,%1,%2,%3}, {%4,%5,%6,%7}, {%8,%9}, {%0,%1,%2,%3};"
        : "+f"(c[0]), "+f"(c[1]), "+f"(c[2]), "+f"(c[3])
        : "r"(a[0]), "r"(a[1]), "r"(a[2]), "r"(a[3]),
          "r"(b[0]), "r"(b[1]));
}
// swizzled byte offset: row r (64-half rows = 8 x 16B units), unit u
__device__ __forceinline__ uint32_t swz(int r, int u) {
    return (uint32_t)(((r << 3) + (u ^ (r & 7))) << 4);
}

// ---------------- merged PROLOGUE: transposes + bias concat + LN1 ------------
// blocks [0,12288): weight transposes (fp32 -> fp16)
// blocks [12288,12300): QKV bias concat
// blocks [12300,20492): LN1 rows
__global__ void __launch_bounds__(256) prologue_kernel(
    const float* __restrict__ x,
    const float* __restrict__ ln1w, const float* __restrict__ ln1b,
    const float* __restrict__ Wq, const float* __restrict__ Wk,
    const float* __restrict__ Wv, const float* __restrict__ Wo,
    const float* __restrict__ W1, const float* __restrict__ W2,
    const float* __restrict__ bq, const float* __restrict__ bk,
    const float* __restrict__ bv,
    __half* __restrict__ wT, float* __restrict__ bqkv,
    __half* __restrict__ H) {
    __shared__ float tbuf[32][33];
    __shared__ float red[16];
    int id = blockIdx.x;
    int tid = threadIdx.x;

    if (id < 12288) {                       // ---- transpose ----
        const float* src;
        __half* dst;
        int R, Ncols;
        if (id < 4096) {
            int seg = id >> 10;
            id &= 1023;
            src = (seg == 0) ? Wq : (seg == 1) ? Wk : (seg == 2) ? Wv : Wo;
            dst = wT + (size_t)seg * CC * CC;
            R = CC; Ncols = CC;
        } else if (id < 8192) {
            id -= 4096;
            src = W1; dst = wT + (size_t)4 * CC * CC;
            R = CC; Ncols = WFF;
        } else {
            id -= 8192;
            src = W2; dst = wT + (size_t)4 * CC * CC + (size_t)CC * WFF;
            R = WFF; Ncols = CC;
        }
        int txt = Ncols >> 5;
        int bx = (id % txt) << 5, by = (id / txt) << 5;
        int tx = tid & 31, ty = tid >> 5;
#pragma unroll
        for (int i = 0; i < 32; i += 8)
            tbuf[ty + i][tx] = src[(size_t)(by + ty + i) * Ncols + bx + tx];
        __syncthreads();
#pragma unroll
        for (int i = 0; i < 32; i += 8)
            dst[(size_t)(bx + ty + i) * R + by + tx] = __float2half(tbuf[tx][ty + i]);
    } else if (id < 12300) {                // ---- bias concat ----
        int t = (id - 12288) * 256 + tid;
        if (t < CC)            bqkv[t] = bq[t];
        else if (t < 2 * CC)   bqkv[t] = bk[t - CC];
        else if (t < 3 * CC)   bqkv[t] = bv[t - 2 * CC];
    } else {                                // ---- LN1 ----
        int row = id - 12300;
        const float* xr = x + (size_t)row * CC;
        float4 v = *(const float4*)(xr + tid * 4);
        float s  = v.x + v.y + v.z + v.w;
        float ss = v.x*v.x + v.y*v.y + v.z*v.z + v.w*v.w;
#pragma unroll
        for (int o = 16; o; o >>= 1) {
            s  += __shfl_down_sync(0xffffffffu, s,  o);
            ss += __shfl_down_sync(0xffffffffu, ss, o);
        }
        if ((tid & 31) == 0) { red[tid >> 5] = s; red[8 + (tid >> 5)] = ss; }
        __syncthreads();
        if (tid == 0) {
            float a = 0.f, c = 0.f;
#pragma unroll
            for (int i = 0; i < 8; i++) { a += red[i]; c += red[8 + i]; }
            float mean = a * (1.f / CC);
            float var  = c * (1.f / CC) - mean * mean;
            red[0] = mean;
            red[1] = rsqrtf(var + 1e-5f);
        }
        __syncthreads();
        float mean = red[0], rstd = red[1];
        float4 w4 = *(const float4*)(ln1w + tid * 4);
        float4 b4 = *(const float4*)(ln1b + tid * 4);
        __half2* op = (__half2*)(H + (size_t)row * CC);
        op[tid * 2 + 0] = __floats2half2_rn((v.x - mean) * rstd * w4.x + b4.x,
                                            (v.y - mean) * rstd * w4.y + b4.y);
        op[tid * 2 + 1] = __floats2half2_rn((v.z - mean) * rstd * w4.z + b4.z,
                                            (v.w - mean) * rstd * w4.w + b4.w);
    }
}

// ---------------- LayerNorm (fp16 in, fp16 out) for LN2 ----------------------
__global__ void __launch_bounds__(256) ln_h(
    const __half* __restrict__ X, const float* __restrict__ gw,
    const float* __restrict__ gb, __half* __restrict__ O) {
    __shared__ float red[16];
    int row = blockIdx.x;
    int t = threadIdx.x;
    const __half2* xr = (const __half2*)(X + (size_t)row * CC);
    __half2 h0 = xr[t * 2], h1 = xr[t * 2 + 1];
    float2 fa = __half22float2(h0), fb = __half22float2(h1);
    float s  = fa.x + fa.y + fb.x + fb.y;
    float ss = fa.x*fa.x + fa.y*fa.y + fb.x*fb.x + fb.y*fb.y;
#pragma unroll
    for (int o = 16; o; o >>= 1) {
        s  += __shfl_down_sync(0xffffffffu, s,  o);
        ss += __shfl_down_sync(0xffffffffu, ss, o);
    }
    if ((t & 31) == 0) { red[t >> 5] = s; red[8 + (t >> 5)] = ss; }
    __syncthreads();
    if (t == 0) {
        float a = 0.f, c = 0.f;
#pragma unroll
        for (int i = 0; i < 8; i++) { a += red[i]; c += red[8 + i]; }
        float mean = a * (1.f / CC);
        float var  = c * (1.f / CC) - mean * mean;
        red[0] = mean;
        red[1] = rsqrtf(var + 1e-5f);
    }
    __syncthreads();
    float mean = red[0], rstd = red[1];
    float4 w4 = *(const float4*)(gw + t * 4);
    float4 b4 = *(const float4*)(gb + t * 4);
    __half2* op = (__half2*)(O + (size_t)row * CC);
    op[t * 2 + 0] = __floats2half2_rn((fa.x - mean) * rstd * w4.x + b4.x,
                                      (fa.y - mean) * rstd * w4.y + b4.y);
    op[t * 2 + 1] = __floats2half2_rn((fb.x - mean) * rstd * w4.z + b4.z,
                                      (fb.y - mean) * rstd * w4.w + b4.w);
}

// ---------------- fp16 mma GEMM: tile 128x128, BK=64, 3-stage (R6/R10) -------
// A: [M,K] fp16 RM.  Bt: [N,K] fp16 RM.
// EPI: 0 = bias -> fp16 | 1 = bias+relu -> fp16
//      2 = bias + fp32 residual -> fp16 | 3 = bias + fp16 residual -> fp32
#define GSMEM_BYTES (3 * 32768)

template <int EPI>
__global__ void __launch_bounds__(256, 2) gemm_h(
    const __half* __restrict__ A, const __half* __restrict__ Bt,
    const float* __restrict__ bias, const void* __restrict__ res,
    void* __restrict__ Cout_, int M, int N, int K) {
    extern __shared__ char smc[];
    int tid = threadIdx.x, wid = tid >> 5, lane = tid & 31;
    int gid = lane >> 2, tig = lane & 3;
    int wm = wid >> 1, wn = wid & 1;
    int bm = blockIdx.y << 7, bn = blockIdx.x << 7;

    const __half* Ag = A  + (size_t)bm * K;
    const __half* Bg = Bt + (size_t)bn * K;
    uint32_t smb = smem_u32(smc);

    auto load_chunk = [&](int c, int b) {
        const __half* Ac = Ag + c * 64;
        const __half* Bc = Bg + c * 64;
        uint32_t ab = smb + b * 32768;
        uint32_t bb = ab + 16384;
#pragma unroll
        for (int i = 0; i < 4; i++) {
            int idx = tid + (i << 8);
            int row = idx >> 3, u = idx & 7;
            uint32_t off = swz(row, u);
            cp16(ab + off, Ac + (size_t)row * K + (u << 3));
            cp16(bb + off, Bc + (size_t)row * K + (u << 3));
        }
    };

    float acc[2][8][4];
#pragma unroll
    for (int mt = 0; mt < 2; mt++)
#pragma unroll
        for (int nt = 0; nt < 8; nt++)
#pragma unroll
            for (int r = 0; r < 4; r++) acc[mt][nt][r] = 0.f;

    const int l15 = lane & 15, l7 = lane & 7;
    const int aU = lane >> 4;
    const int bR = (lane >> 4) << 3;
    const int bU = (lane >> 3) & 1;

    int nc = K >> 6;
    load_chunk(0, 0);
    CP_COMMIT();
    if (nc > 1) { load_chunk(1, 1); CP_COMMIT(); }

    for (int c = 0; c < nc; c++) {
        if (c + 1 < nc) CP_WAIT1(); else CP_WAIT0();
        __syncthreads();
        if (c + 2 < nc) {
            load_chunk(c + 2, (c + 2) % 3);
            CP_COMMIT();
        }
        uint32_t sA = smb + (c % 3) * 32768;
        uint32_t sB = sA + 16384;
#pragma unroll
        for (int ks = 0; ks < 4; ks++) {
            uint32_t aF[2][4], bF[8][2];
#pragma unroll
            for (int mt = 0; mt < 2; mt++) {
                int r = wm * 32 + mt * 16 + l15;
                ldsm4(aF[mt], sA + swz(r, 2 * ks + aU));
            }
#pragma unroll
            for (int ntp = 0; ntp < 4; ntp++) {
                int r = wn * 64 + ntp * 16 + l7 + bR;
                uint32_t t4[4];
                ldsm4(t4, sB + swz(r, 2 * ks + bU));
                bF[2 * ntp][0] = t4[0]; bF[2 * ntp][1] = t4[1];
                bF[2 * ntp + 1][0] = t4[2]; bF[2 * ntp + 1][1] = t4[3];
            }
#pragma unroll
            for (int mt = 0; mt < 2; mt++)
#pragma unroll
                for (int nt = 0; nt < 8; nt++)
                    mma_f16(acc[mt][nt], aF[mt], bF[nt]);
        }
        __syncthreads();
    }

    // ---- epilogue ----
#pragma unroll
    for (int mt = 0; mt < 2; mt++) {
        int r0 = bm + wm * 32 + mt * 16 + gid;
#pragma unroll
        for (int half = 0; half < 2; half++) {
            int row = r0 + half * 8;
#pragma unroll
            for (int nt = 0; nt < 8; nt++) {
                int col = bn + wn * 64 + nt * 8 + tig * 2;
                float2 bv = *(const float2*)(bias + col);
                float ox = acc[mt][nt][half * 2 + 0] + bv.x;
                float oy = acc[mt][nt][half * 2 + 1] + bv.y;
                if (EPI == 1) { ox = fmaxf(ox, 0.f); oy = fmaxf(oy, 0.f); }
                if (EPI == 2) {
                    float2 rr = *(const float2*)((const float*)res +
                                                 (size_t)row * N + col);
                    __half* Co = (__half*)Cout_;
                    *(__half2*)(Co + (size_t)row * N + col) =
                        __floats2half2_rn(ox + rr.x, oy + rr.y);
                } else if (EPI == 3) {
                    __half2 rh = *(const __half2*)((const __half*)res +
                                                   (size_t)row * N + col);
                    float2 rf = __half22float2(rh);
                    float* Co = (float*)Cout_;
                    *(float2*)(Co + (size_t)row * N + col) =
                        make_float2(ox + rf.x, oy + rf.y);
                } else {
                    __half* Co = (__half*)Cout_;
                    *(__half2*)(Co + (size_t)row * N + col) =
                        __floats2half2_rn(ox, oy);
                }
            }
        }
    }
}

// ---------------- fp16 flash attention: BQ=128, BK=64, 3-buffer KV ring -----
// Q pre-scaled by 0.125*log2(e): softmax runs in base-2. LPT block order.
#define AS_Q 0
#define AS_K 16384
#define AS_V 40960
#define AS_P 65536
#define ASMEM_BYTES 81920
#define QSCALE (0.125f * 1.4426950408889634f)

__global__ void __launch_bounds__(256) attn_h(
    const __half* __restrict__ QKV, __half* __restrict__ Y) {
    extern __shared__ char smc[];
    uint32_t smb = smem_u32(smc);
    int qt = (gridDim.x - 1) - blockIdx.x;   // heavy tiles first
    int hh = blockIdx.y, b = blockIdx.z;
    int tid = threadIdx.x, wid = tid >> 5, lane = tid & 31;
    int gid = lane >> 2, tig = lane & 3;
    int q0 = qt * 128;

    const __half* Qg = QKV + (size_t)b * TT * C3 + hh * DD;
    const __half* Kg = Qg + CC;
    const __half* Vg = Qg + 2 * CC;

    const int l15 = lane & 15, l7 = lane & 7;
    const int aU = lane >> 4;
    const int bR = (lane >> 4) << 3;
    const int bU = (lane >> 3) & 1;

    auto loadKV = [&](int t, int bf) {
        const __half* Kt = Kg + (size_t)(t * 64) * C3;
        const __half* Vt = Vg + (size_t)(t * 64) * C3;
        uint32_t dk = smb + AS_K + bf * 8192;
        uint32_t dv = smb + AS_V + bf * 8192;
#pragma unroll
        for (int i = 0; i < 2; i++) {
            int idx = tid + (i << 8);
            int row = idx >> 3, u = idx & 7;
            uint32_t off = swz(row, u);
            cp16(dk + off, Kt + (size_t)row * C3 + (u << 3));
            cp16(dv + off, Vt + (size_t)row * C3 + (u << 3));
        }
    };

    int ntiles = 2 * qt + 2;
    {   // Q tile: load, scale, store swizzled
        const __half2 qs2 = __float2half2_rn(QSCALE);
#pragma unroll
        for (int i = 0; i < 4; i++) {
            int idx = tid + (i << 8);
            int row = idx >> 3, u = idx & 7;
            const __half2* src = (const __half2*)(Qg + (size_t)(q0 + row) * C3 + (u << 3));
            __half2 v0 = __hmul2(src[0], qs2);
            __half2 v1 = __hmul2(src[1], qs2);
            __half2 v2 = __hmul2(src[2], qs2);
            __half2 v3 = __hmul2(src[3], qs2);
            __half2* d = (__half2*)(smc + AS_Q + swz(row, u));
            d[0] = v0; d[1] = v1; d[2] = v2; d[3] = v3;
        }
    }
    loadKV(0, 0);
    CP_COMMIT();
    loadKV(1, 1);
    CP_COMMIT();
    CP_WAIT1();
    __syncthreads();

    uint32_t qf[4][4];
#pragma unroll
    for (int ks = 0; ks < 4; ks++) {
        int r = wid * 16 + l15;
        ldsm4(qf[ks], smb + AS_Q + swz(r, 2 * ks + aU));
    }

    float m_i[2] = {-1e30f, -1e30f}, l_i[2] = {0.f, 0.f};
    float oacc[8][4];
#pragma unroll
    for (int nt = 0; nt < 8; nt++)
#pragma unroll
        for (int r = 0; r < 4; r++) oacc[nt][r] = 0.f;

    const int rbase = q0 + wid * 16 + gid;

    for (int t = 0; t < ntiles; t++) {
        if (t > 0) {
            if (t + 1 < ntiles) CP_WAIT1(); else CP_WAIT0();
            __syncthreads();
        }
        if (t + 2 < ntiles) {
            loadKV(t + 2, (t + 2) % 3);
            CP_COMMIT();
        }
        int k0t = t * 64;
        bool active = (k0t <= q0 + wid * 16 + 15);
        if (active) {
            int bf = t % 3;
            uint32_t sK = smb + AS_K + bf * 8192;
            uint32_t sV = smb + AS_V + bf * 8192;
            float sfr[8][4];
#pragma unroll
            for (int nt = 0; nt < 8; nt++)
#pragma unroll
                for (int r = 0; r < 4; r++) sfr[nt][r] = 0.f;
#pragma unroll
            for (int ks = 0; ks < 4; ks++) {
                uint32_t bF[8][2];
#pragma unroll
                for (int ntp = 0; ntp < 4; ntp++) {
                    int r = ntp * 16 + l7 + bR;
                    uint32_t t4[4];
                    ldsm4(t4, sK + swz(r, 2 * ks + bU));
                    bF[2 * ntp][0] = t4[0]; bF[2 * ntp][1] = t4[1];
                    bF[2 * ntp + 1][0] = t4[2]; bF[2 * ntp + 1][1] = t4[3];
                }
#pragma unroll
                for (int nt = 0; nt < 8; nt++)
                    mma_f16(sfr[nt], qf[ks], bF[nt]);
            }
            if (k0t + 63 > rbase) {
#pragma unroll
                for (int nt = 0; nt < 8; nt++) {
                    int cb = k0t + nt * 8 + tig * 2;
                    if (cb     > rbase)     sfr[nt][0] = -1e30f;
                    if (cb + 1 > rbase)     sfr[nt][1] = -1e30f;
                    if (cb     > rbase + 8) sfr[nt][2] = -1e30f;
                    if (cb + 1 > rbase + 8) sfr[nt][3] = -1e30f;
                }
            }
#pragma unroll
            for (int h = 0; h < 2; h++) {
                float rm = -1e30f;
#pragma unroll
                for (int nt = 0; nt < 8; nt++)
                    rm = fmaxf(rm, fmaxf(sfr[nt][2 * h], sfr[nt][2 * h + 1]));
                rm = fmaxf(rm, __shfl_xor_sync(0xffffffffu, rm, 1));
                rm = fmaxf(rm, __shfl_xor_sync(0xffffffffu, rm, 2));
                float mn = fmaxf(m_i[h], rm);
                float alpha = exp2f(m_i[h] - mn);
                m_i[h] = mn;
                float rs = 0.f;
                int pr = wid * 16 + gid + h * 8;
#pragma unroll
                for (int nt = 0; nt < 8; nt++) {
                    float p0 = exp2f(sfr[nt][2 * h]     - mn);
                    float p1 = exp2f(sfr[nt][2 * h + 1] - mn);
                    rs += p0 + p1;
                    int col = nt * 8 + tig * 2;
                    *(__half2*)(smc + AS_P + swz(pr, col >> 3) + (col & 7) * 2) =
                        __floats2half2_rn(p0, p1);
                    oacc[nt][2 * h]     *= alpha;
                    oacc[nt][2 * h + 1] *= alpha;
                }
                rs += __shfl_xor_sync(0xffffffffu, rs, 1);
                rs += __shfl_xor_sync(0xffffffffu, rs, 2);
                l_i[h] = l_i[h] * alpha + rs;
            }
            __syncwarp();
#pragma unroll
            for (int ks = 0; ks < 4; ks++) {
                uint32_t pf[4];
                {
                    int r = wid * 16 + l15;
                    ldsm4(pf, smb + AS_P + swz(r, 2 * ks + aU));
                }
#pragma unroll
                for (int ntp = 0; ntp < 4; ntp++) {
                    int kk = ks * 16 + l7 + ((lane >> 3) & 1) * 8;
                    uint32_t t4[4];
                    ldsm4t(t4, sV + swz(kk, 2 * ntp + aU));
                    mma_f16(oacc[2 * ntp],     pf, t4);
                    mma_f16(oacc[2 * ntp + 1], pf, t4 + 2);
                }
            }
        }
    }

    __half* Yg = Y + (size_t)b * TT * CC + hh * DD;
#pragma unroll
    for (int h = 0; h < 2; h++) {
        float inv = 1.f / l_i[h];
        __half* yr = Yg + (size_t)(rbase + h * 8) * CC;
#pragma unroll
        for (int nt = 0; nt < 8; nt++) {
            int col = nt * 8 + tig * 2;
            *(__half2*)(yr + col) = __floats2half2_rn(
                oacc[nt][2 * h] * inv, oacc[nt][2 * h + 1] * inv);
        }
    }
}

// ---------------- launch ---------------------------------------------------
extern "C" void kernel_launch(void* const* d_in, const int* in_sizes, int n_in,
                              void* d_out, int out_size) {
    const float* x    = (const float*)d_in[0];
    const float* ln1w = (const float*)d_in[1];
    const float* ln1b = (const float*)d_in[2];
    const float* Wq   = (const float*)d_in[3];
    const float* bq   = (const float*)d_in[4];
    const float* Wk   = (const float*)d_in[5];
    const float* bk   = (const float*)d_in[6];
    const float* Wv   = (const float*)d_in[7];
    const float* bv   = (const float*)d_in[8];
    const float* Wo   = (const float*)d_in[9];
    const float* bo   = (const float*)d_in[10];
    const float* ln2w = (const float*)d_in[11];
    const float* ln2b = (const float*)d_in[12];
    const float* W1   = (const float*)d_in[13];
    const float* b1   = (const float*)d_in[14];
    const float* W2   = (const float*)d_in[15];
    const float* b2   = (const float*)d_in[16];
    float* out = (float*)d_out;

    __half *h, *qkv, *y, *x2, *ff, *wT;
    float *bqkv;
    cudaGetSymbolAddress((void**)&h,    g_h);
    cudaGetSymbolAddress((void**)&qkv,  g_qkv);
    cudaGetSymbolAddress((void**)&y,    g_y);
    cudaGetSymbolAddress((void**)&x2,   g_x2);
    cudaGetSymbolAddress((void**)&ff,   g_ff);
    cudaGetSymbolAddress((void**)&wT,   g_wT);
    cudaGetSymbolAddress((void**)&bqkv, g_bqkv);

    __half* WqkvT = wT;                                  // [3C, C]
    __half* WoT   = WqkvT + (size_t)3 * CC * CC;         // [C, C]
    __half* W1T   = WoT + (size_t)CC * CC;               // [WFF, C]
    __half* W2T   = W1T + (size_t)CC * WFF;              // [C, WFF]

    cudaFuncSetAttribute(attn_h,
                         cudaFuncAttributeMaxDynamicSharedMemorySize, ASMEM_BYTES);
    cudaFuncSetAttribute(gemm_h<0>,
                         cudaFuncAttributeMaxDynamicSharedMemorySize, GSMEM_BYTES);
    cudaFuncSetAttribute(gemm_h<1>,
                         cudaFuncAttributeMaxDynamicSharedMemorySize, GSMEM_BYTES);
    cudaFuncSetAttribute(gemm_h<2>,
                         cudaFuncAttributeMaxDynamicSharedMemorySize, GSMEM_BYTES);
    cudaFuncSetAttribute(gemm_h<3>,
                         cudaFuncAttributeMaxDynamicSharedMemorySize, GSMEM_BYTES);

    // ---- merged prologue: transposes + bias concat + LN1 (ONE launch) ----
    prologue_kernel<<<20492, 256>>>(x, ln1w, ln1b, Wq, Wk, Wv, Wo, W1, W2,
                                    bq, bk, bv, wT, bqkv, h);

    // fused QKV projection (N = 3072)
    gemm_h<0><<<dim3(C3 / 128, MM / 128), 256, GSMEM_BYTES>>>(
        h, WqkvT, bqkv, nullptr, qkv, MM, C3, CC);
    // causal attention
    attn_h<<<dim3(TT / 128, HH, BB), 256, ASMEM_BYTES>>>(qkv, y);
    // output projection + residual -> fp16 trunk x2
    dim3 g1(CC / 128, MM / 128);
    gemm_h<2><<<g1, 256, GSMEM_BYTES>>>(y, WoT, bo, x, x2, MM, CC, CC);
    // LN2 (fp16 in)
    ln_h<<<MM, 256>>>(x2, ln2w, ln2b, h);
    // FF1 (relu)
    gemm_h<1><<<dim3(WFF / 128, MM / 128), 256, GSMEM_BYTES>>>(
        h, W1T, b1, nullptr, ff, MM, WFF, CC);
    // FF2 + fp16 residual -> fp32 out
    gemm_h<3><<<g1, 256, GSMEM_BYTES>>>(ff, W2T, b2, x2, out, MM, CC, WFF);
}